// round 16
// baseline (speedup 1.0000x reference)
#include <cuda_runtime.h>
#include <cuda_bf16.h>
#include <cstdint>

// Problem constants (fixed by setup_inputs)
#define HPM       8
#define NUM_PAGES 4096
#define PAGE_SIZE 16
#define DPM       128
#define MAX_SEQS  8
#define MAX_PPS   256
#define D4        (DPM / 4)                                    // 32 float4 per row
#define PAGES_ELEMS (2LL * HPM * NUM_PAGES * PAGE_SIZE * DPM)  // 134,217,728 floats
#define INNER_F4  (HPM * NUM_PAGES * PAGE_SIZE * D4)           // 1<<24 float4 per tensor
#define TOTAL_F4  (2u * INNER_F4)                              // 1<<25
#define NBLOCKS   (TOTAL_F4 / 512u)                            // 65536, one page per block

// Scratch (device globals — zero-init at load; reset by last block each run)
__device__ int      g_blk_of_page[NUM_PAGES];  // -1 => passthrough, else block index
__device__ unsigned g_ready;                   // setup-done flag
__device__ unsigned g_done;                    // completion counter

__device__ __forceinline__ unsigned ld_acquire(const unsigned* p) {
    unsigned v;
    asm volatile("ld.global.acquire.gpu.u32 %0, [%1];" : "=r"(v) : "l"(p) : "memory");
    return v;
}
__device__ __forceinline__ void st_release(unsigned* p, unsigned v) {
    asm volatile("st.global.release.gpu.u32 [%0], %1;" :: "l"(p), "r"(v) : "memory");
}

// ---------------------------------------------------------------------------
// Single fused kernel, 65536 x 128 threads (one page per block — R14's
// proven copy body). Block 0: register-light two-pass first-fit setup +
// small outputs, then st.release(g_ready). Other blocks: spin-acquire
// (nanosleep backoff), then copy. Epilogue: ONE fence-free atomicAdd per
// block; the last block resets the flags for the next graph replay.
// NO __threadfence anywhere (R3's 32768 CCTL.IVALL L1-flushes removed).
// ---------------------------------------------------------------------------
__global__ void __launch_bounds__(128, 16)
fused_pages_kernel(const float4* __restrict__ key,          // [1, S, H, D]
                   const float4* __restrict__ value,
                   const float4* __restrict__ key_pages,    // [H, P, PS, D]
                   const float4* __restrict__ value_pages,
                   const int*    __restrict__ page_indices,
                   const int*    __restrict__ seq_page_indices,
                   const int*    __restrict__ slot_p,
                   const int*    __restrict__ true_length_p,
                   float4* __restrict__ out,                 // [2, H, P, PS, D]
                   float*  __restrict__ out_pi,              // [4096]
                   float*  __restrict__ out_spi)             // [8, 256]
{
    const unsigned bIdx = blockIdx.x;
    const int tid = threadIdx.x;

    if (bIdx == 0) {
        // ---------------- Setup (block 0 only; 128 threads, 32 pages each) -----
        __shared__ int s_base[4];
        __shared__ int s_pob[MAX_PPS];
        const int lane = tid & 31;
        const int wrp  = tid >> 5;
        const int4* pi4 = (const int4*)page_indices;

        // Pass 1: count free pages (streaming, no big register arrays)
        int cnt = 0;
#pragma unroll
        for (int k = 0; k < 8; k++) {
            int4 v = __ldg(&pi4[tid * 8 + k]);
            int bp = tid * 32 + k * 4;
            cnt += (bp >= 1) && (v.x == 0);
            cnt += (v.y == 0);
            cnt += (v.z == 0);
            cnt += (v.w == 0);
        }
        const int tl = __ldg(true_length_p);

        int incl = cnt;
#pragma unroll
        for (int off = 1; off < 32; off <<= 1) {
            int n = __shfl_up_sync(0xffffffffu, incl, off);
            if (lane >= off) incl += n;
        }
        if (lane == 31) s_base[wrp] = incl;
        __syncthreads();
        if (wrp == 0 && lane < 4) {
            int v = s_base[lane];
            int s = v;
#pragma unroll
            for (int off = 1; off < 4; off <<= 1) {
                int n = __shfl_up_sync(0xfu, s, off);
                if (lane >= off) s += n;
            }
            s_base[lane] = s - v;
        }
        __syncthreads();

        int run = s_base[wrp] + (incl - cnt);

        int nb = (tl + PAGE_SIZE - 1) / PAGE_SIZE;
        if (nb > MAX_PPS) nb = MAX_PPS;

        // Pass 2: reload (L2 hits), assign, publish table + out_pi
#pragma unroll
        for (int k = 0; k < 8; k++) {
            int4 v = __ldg(&pi4[tid * 8 + k]);
            int pvals[4] = { v.x, v.y, v.z, v.w };
            float po[4];
#pragma unroll
            for (int q = 0; q < 4; q++) {
                int p  = tid * 32 + k * 4 + q;
                int fr = (p >= 1) && (pvals[q] == 0);
                int b  = -1;
                if (fr) {
                    if (run < nb) { b = run; s_pob[run] = p; }
                    run++;
                }
                g_blk_of_page[p] = b;
                po[q] = (b >= 0) ? 1.0f : (float)pvals[q];
            }
            ((float4*)out_pi)[tid * 8 + k] = make_float4(po[0], po[1], po[2], po[3]);
        }
        __syncthreads();   // s_pob + table writes complete block-wide

        // seq_page_indices output (16 per thread)
        const int slot = __ldg(slot_p);
        const int4* spi4 = (const int4*)seq_page_indices;
#pragma unroll
        for (int k = 0; k < 4; k++) {
            int4 sv = __ldg(&spi4[tid * 4 + k]);
            int s4[4] = { sv.x, sv.y, sv.z, sv.w };
            float o4[4];
#pragma unroll
            for (int q = 0; q < 4; q++) {
                int i = tid * 16 + k * 4 + q;
                int r = i >> 8, c = i & 255;
                float vv = (float)s4[q];
                if (r == slot && c < nb) vv = (float)s_pob[c];
                o4[q] = vv;
            }
            ((float4*)out_spi)[tid * 4 + k] = make_float4(o4[0], o4[1], o4[2], o4[3]);
        }

        __syncthreads();                    // all setup work done block-wide
        if (tid == 0) st_release(&g_ready, 1u);   // publish (no CCTL.IVALL)
    } else {
        // ---------------- Waiters: spin-acquire once ----------------
        if (tid == 0) {
            while (ld_acquire(&g_ready) == 0u) __nanosleep(256);
        }
        __syncthreads();
    }

    // ---------------- Copy: R14 body verbatim (one page per block) ----------
    const unsigned base = bIdx * 512u + tid;

    const unsigned p = bIdx & (NUM_PAGES - 1);        // page   (block-uniform)
    const unsigned h = (bIdx >> 12) & (HPM - 1);      // head   (block-uniform)
    const unsigned t = bIdx >> 15;                    // tensor (block-uniform)

    const float4* __restrict__ kv    = t ? value       : key;
    const float4* __restrict__ pages = t ? value_pages : key_pages;

    const int b = g_blk_of_page[p];                   // one warp-uniform load per block

    const float4* srcs[4];
#pragma unroll
    for (int j = 0; j < 4; j++) {
        unsigned idx = base + j * 128u;
        unsigned d4  = idx & (D4 - 1);
        unsigned row = (idx >> 5) & (PAGE_SIZE - 1);

        unsigned s    = (unsigned)b * PAGE_SIZE + row;
        unsigned offA = (s * HPM + h) * D4 + d4;      // key/value (transpose folded)
        unsigned offB = idx & (INNER_F4 - 1);         // pass-through pages
        srcs[j] = (b >= 0) ? (kv + offA) : (pages + offB);
    }

    float4 vals[4];
#pragma unroll
    for (int j = 0; j < 4; j++) vals[j] = __ldcs(srcs[j]);   // 4 back-to-back LDG.128.CS

#pragma unroll
    for (int j = 0; j < 4; j++) __stcs(&out[base + j * 128u], vals[j]);

    // ---------------- Epilogue: fence-free replay-safe reset ----------------
    __syncthreads();   // all threads of this block are past the spin & stores issued
    if (tid == 0) {
        unsigned d = atomicAdd(&g_done, 1u);
        if (d == NBLOCKS - 1u) {     // strictly last: every block passed the spin
            g_done  = 0u;
            g_ready = 0u;            // clean state for the next graph replay
        }
    }
}

// ---------------------------------------------------------------------------
// Launch — ONE kernel node.
// Inputs: key, value, key_pages, value_pages, page_indices, seq_page_indices,
//         slot, true_length
// Output: concat(pages[2,H,P,PS,D], page_indices[4096], seq_page_indices[2048])
// ---------------------------------------------------------------------------
extern "C" void kernel_launch(void* const* d_in, const int* in_sizes, int n_in,
                              void* d_out, int out_size)
{
    const float* key          = (const float*)d_in[0];
    const float* value        = (const float*)d_in[1];
    const float* key_pages    = (const float*)d_in[2];
    const float* value_pages  = (const float*)d_in[3];
    const int*   page_indices = (const int*)d_in[4];
    const int*   seq_page_ind = (const int*)d_in[5];
    const int*   slot         = (const int*)d_in[6];
    const int*   true_length  = (const int*)d_in[7];

    float* out_pages = (float*)d_out;
    float* out_pi    = out_pages + PAGES_ELEMS;
    float* out_spi   = out_pi + NUM_PAGES;

    fused_pages_kernel<<<NBLOCKS, 128>>>(
        (const float4*)key, (const float4*)value,
        (const float4*)key_pages, (const float4*)value_pages,
        page_indices, seq_page_ind, slot, true_length,
        (float4*)out_pages, out_pi, out_spi);
}

// round 17
// speedup vs baseline: 1.4905x; 1.4905x over previous
#include <cuda_runtime.h>
#include <cuda_bf16.h>
#include <cstdint>

// Problem constants (fixed by setup_inputs)
#define HPM       8
#define NUM_PAGES 4096
#define PAGE_SIZE 16
#define DPM       128
#define MAX_SEQS  8
#define MAX_PPS   256
#define D4        (DPM / 4)                                    // 32 float4 per row
#define PAGES_ELEMS (2LL * HPM * NUM_PAGES * PAGE_SIZE * DPM)  // 134,217,728 floats
#define INNER_F4  (HPM * NUM_PAGES * PAGE_SIZE * D4)           // 1<<24 float4 per tensor
#define TOTAL_F4  (2u * INNER_F4)                              // 1<<25

// Scratch (device global — no allocation allowed)
__device__ int g_blk_of_page[NUM_PAGES];   // -1 => keep old contents, else block index

// ---------------------------------------------------------------------------
// Kernel A: first-fit allocation, TWO independent blocks run concurrently:
//   block 0: scan -> g_blk_of_page table + out_pi
//   block 1: scan -> private page_of_block (smem) -> out_spi
// Wall time = scan + max(tail) instead of scan + sum(tails).
// ---------------------------------------------------------------------------
__global__ void __launch_bounds__(256)
setup_kernel(const int* __restrict__ page_indices,
             const int* __restrict__ seq_page_indices,
             const int* __restrict__ slot_p,
             const int* __restrict__ true_length_p,
             float* __restrict__ out_pi,
             float* __restrict__ out_spi)
{
    __shared__ int s_base[8];
    __shared__ int s_pob[MAX_PPS];     // used by block 1 only
    const int tid  = threadIdx.x;
    const int lane = tid & 31;
    const int wrp  = tid >> 5;
    const unsigned bIdx = blockIdx.x;

    // ---- Shared prologue: load 16 pages/thread, count free ----
    const int4* pi4 = (const int4*)page_indices;
    int4 pv[4];
#pragma unroll
    for (int k = 0; k < 4; k++) pv[k] = __ldg(&pi4[tid * 4 + k]);
    const int tl = __ldg(true_length_p);

    int vals[16], fl[16];
    int cnt = 0;
#pragma unroll
    for (int k = 0; k < 4; k++) {
        vals[k*4+0] = pv[k].x; vals[k*4+1] = pv[k].y;
        vals[k*4+2] = pv[k].z; vals[k*4+3] = pv[k].w;
    }
#pragma unroll
    for (int j = 0; j < 16; j++) {
        int p = tid * 16 + j;
        fl[j] = (p >= 1) && (vals[j] == 0);
        cnt += fl[j];
    }

    // Warp inclusive scan of per-thread counts
    int incl = cnt;
#pragma unroll
    for (int off = 1; off < 32; off <<= 1) {
        int n = __shfl_up_sync(0xffffffffu, incl, off);
        if (lane >= off) incl += n;
    }
    if (lane == 31) s_base[wrp] = incl;
    __syncthreads();

    if (wrp == 0 && lane < 8) {
        int v = s_base[lane];
        int s = v;
#pragma unroll
        for (int off = 1; off < 8; off <<= 1) {
            int n = __shfl_up_sync(0xffu, s, off);
            if (lane >= off) s += n;
        }
        s_base[lane] = s - v;
    }
    __syncthreads();

    int run = s_base[wrp] + (incl - cnt);   // exclusive rank of this thread's first page

    int nb = (tl + PAGE_SIZE - 1) / PAGE_SIZE;
    if (nb > MAX_PPS) nb = MAX_PPS;

    if (bIdx == 0) {
        // ---- Block 0: publish table + out_pi ----
        float pi_out[16];
#pragma unroll
        for (int j = 0; j < 16; j++) {
            int p = tid * 16 + j;
            int b = -1;
            if (fl[j]) {
                if (run < nb) b = run;
                run++;
            }
            g_blk_of_page[p] = b;
            pi_out[j] = (b >= 0) ? 1.0f : (float)vals[j];
        }
#pragma unroll
        for (int k = 0; k < 4; k++) {
            float4 v = make_float4(pi_out[k*4+0], pi_out[k*4+1], pi_out[k*4+2], pi_out[k*4+3]);
            ((float4*)out_pi)[tid * 4 + k] = v;
        }
    } else {
        // ---- Block 1: private page_of_block -> out_spi ----
        const int4* spi4 = (const int4*)seq_page_indices;
        int4 sv[2];
#pragma unroll
        for (int k = 0; k < 2; k++) sv[k] = __ldg(&spi4[tid * 2 + k]);
        const int slot = __ldg(slot_p);

#pragma unroll
        for (int j = 0; j < 16; j++) {
            int p = tid * 16 + j;
            if (fl[j]) {
                if (run < nb) s_pob[run] = p;
                run++;
            }
        }
        __syncthreads();   // s_pob ready

        int svals[8] = { sv[0].x, sv[0].y, sv[0].z, sv[0].w,
                         sv[1].x, sv[1].y, sv[1].z, sv[1].w };
#pragma unroll
        for (int j = 0; j < 8; j++) {
            int i = tid * 8 + j;
            int r = i >> 8, c = i & 255;
            float v = (float)svals[j];
            if (r == slot && c < nb) v = (float)s_pob[c];
            out_spi[i] = v;
        }
    }
}

// ---------------------------------------------------------------------------
// Kernel B: assemble [2, H, P, PS, D] — measured-best body (150.6us,
// DRAM 85.5%, regs 22, occ 88%). 128-thread blocks, one page per block:
// t/h/p/b all block-uniform; 4 independent LDG.128.CS -> 4 STG.128.CS, exit.
// At the LTS chip-throughput cap (~6.78 TB/s on 1.02 GB) — the copy floor.
// ---------------------------------------------------------------------------
__global__ void __launch_bounds__(128)
assemble_pages_kernel(const float4* __restrict__ key,        // [1, S, H, D]
                      const float4* __restrict__ value,
                      const float4* __restrict__ key_pages,  // [H, P, PS, D]
                      const float4* __restrict__ value_pages,
                      float4* __restrict__ out)               // [2, H, P, PS, D]
{
    const unsigned bIdx = blockIdx.x;                 // < 65536
    const unsigned base = bIdx * 512u + threadIdx.x;  // block covers 512 f4 (one page)

    const unsigned p = bIdx & (NUM_PAGES - 1);        // page   (block-uniform)
    const unsigned h = (bIdx >> 12) & (HPM - 1);      // head   (block-uniform)
    const unsigned t = bIdx >> 15;                    // tensor (block-uniform)

    const float4* __restrict__ kv    = t ? value       : key;
    const float4* __restrict__ pages = t ? value_pages : key_pages;

    const int b = g_blk_of_page[p];                   // one warp-uniform load per block

    const float4* srcs[4];
#pragma unroll
    for (int j = 0; j < 4; j++) {
        unsigned idx = base + j * 128u;
        unsigned d4  = idx & (D4 - 1);
        unsigned row = (idx >> 5) & (PAGE_SIZE - 1);

        unsigned s    = (unsigned)b * PAGE_SIZE + row;
        unsigned offA = (s * HPM + h) * D4 + d4;      // key/value (transpose folded)
        unsigned offB = idx & (INNER_F4 - 1);         // pass-through pages
        srcs[j] = (b >= 0) ? (kv + offA) : (pages + offB);
    }

    float4 vals[4];
#pragma unroll
    for (int j = 0; j < 4; j++) vals[j] = __ldcs(srcs[j]);   // 4 back-to-back LDG.128.CS

#pragma unroll
    for (int j = 0; j < 4; j++) __stcs(&out[base + j * 128u], vals[j]);
}

// ---------------------------------------------------------------------------
// Launch — two plain kernel nodes (measured-best structure).
// Inputs: key, value, key_pages, value_pages, page_indices, seq_page_indices,
//         slot, true_length
// Output: concat(pages[2,H,P,PS,D], page_indices[4096], seq_page_indices[2048])
// ---------------------------------------------------------------------------
extern "C" void kernel_launch(void* const* d_in, const int* in_sizes, int n_in,
                              void* d_out, int out_size)
{
    const float* key          = (const float*)d_in[0];
    const float* value        = (const float*)d_in[1];
    const float* key_pages    = (const float*)d_in[2];
    const float* value_pages  = (const float*)d_in[3];
    const int*   page_indices = (const int*)d_in[4];
    const int*   seq_page_ind = (const int*)d_in[5];
    const int*   slot         = (const int*)d_in[6];
    const int*   true_length  = (const int*)d_in[7];

    float* out_pages = (float*)d_out;
    float* out_pi    = out_pages + PAGES_ELEMS;
    float* out_spi   = out_pi + NUM_PAGES;

    setup_kernel<<<2, 256>>>(page_indices, seq_page_ind, slot, true_length,
                             out_pi, out_spi);

    assemble_pages_kernel<<<TOTAL_F4 / 512u, 128>>>(
        (const float4*)key, (const float4*)value,
        (const float4*)key_pages, (const float4*)value_pages,
        (float4*)out_pages);
}